// round 1
// baseline (speedup 1.0000x reference)
#include <cuda_runtime.h>
#include <cstdint>

#define UNITS 65
#define G4    260          // 4*UNITS
#define BATCH 50
#define SEQ   8192
#define NROWS (BATCH * SEQ)   // 409600

// ---------------- scratch (device globals; no runtime allocation) ----------------
__device__ float g_zpre[(size_t)NROWS * G4];   // x@W + b, precomputed per (b,t)
__device__ float g_h3[(size_t)NROWS * UNITS];  // layer-3 hidden states (ys)

// ---------------- f32x2 helpers (Blackwell packed fp32 FMA) ----------------
__device__ __forceinline__ unsigned long long pack2(float lo, float hi) {
    unsigned long long v;
    asm("mov.b64 %0, {%1, %2};" : "=l"(v) : "f"(lo), "f"(hi));
    return v;
}
__device__ __forceinline__ unsigned long long ffma2(unsigned long long a,
                                                    unsigned long long b,
                                                    unsigned long long c) {
    unsigned long long d;
    asm("fma.rn.f32x2 %0, %1, %2, %3;" : "=l"(d) : "l"(a), "l"(b), "l"(c));
    return d;
}
__device__ __forceinline__ float hsum4(unsigned long long a0, unsigned long long a1) {
    float x0, x1, y0, y1;
    asm("mov.b64 {%0, %1}, %2;" : "=f"(x0), "=f"(x1) : "l"(a0));
    asm("mov.b64 {%0, %1}, %2;" : "=f"(y0), "=f"(y1) : "l"(a1));
    return (x0 + x1) + (y0 + y1);
}

// dot over K=65 (padded to 66 with zero): sh must be 16B-aligned float[68] with
// sh[65..67] == 0; col[33] holds weight pairs (col[32].hi == 0).
__device__ __forceinline__ void dot33(const float* __restrict__ sh,
                                      const unsigned long long* col,
                                      unsigned long long& a0,
                                      unsigned long long& a1) {
    const ulonglong2* hp = reinterpret_cast<const ulonglong2*>(sh);
#pragma unroll
    for (int m = 0; m < 16; m++) {
        ulonglong2 p = hp[m];
        a0 = ffma2(p.x, col[2 * m + 0], a0);
        a1 = ffma2(p.y, col[2 * m + 1], a1);
    }
    unsigned long long last = *reinterpret_cast<const unsigned long long*>(sh + 64);
    a0 = ffma2(last, col[32], a0);
}

// ---------------- fast activations (ex2/rcp approx: ~1e-6 rel err) ----------------
__device__ __forceinline__ float fast_ex2(float x) {
    float y; asm("ex2.approx.f32 %0, %1;" : "=f"(y) : "f"(x)); return y;
}
__device__ __forceinline__ float fast_rcp(float x) {
    float y; asm("rcp.approx.f32 %0, %1;" : "=f"(y) : "f"(x)); return y;
}
#define LOG2E 1.4426950408889634f
__device__ __forceinline__ float sigm_f(float x) {
    return fast_rcp(1.0f + fast_ex2(-x * LOG2E));
}
__device__ __forceinline__ float tanh_f(float x) {
    // tanh(x) = 1 - 2/(1 + e^{2x}); saturates correctly via inf/0 at extremes
    return fmaf(-2.0f, fast_rcp(1.0f + fast_ex2(2.0f * LOG2E * x)), 1.0f);
}

// ---------------- kernel 1: zpre = x @ W + b  (all rows, parallel) ----------------
__global__ void __launch_bounds__(G4) pre_kernel(const float* __restrict__ x,
                                                 const float* __restrict__ W,
                                                 const float* __restrict__ b) {
    const int tid = threadIdx.x;           // 0..259  -> gate column
    const int rsub = tid / UNITS;          // 0..3    (x-row loader role)
    const int jl = tid - rsub * UNITS;     // 0..64

    unsigned long long wcol[33];
#pragma unroll
    for (int m = 0; m < 32; m++)
        wcol[m] = pack2(W[(2 * m) * G4 + tid], W[(2 * m + 1) * G4 + tid]);
    wcol[32] = pack2(W[64 * G4 + tid], 0.0f);
    const float bj = b[tid];

    __shared__ __align__(16) float sh_x[4][68];
    if (tid < 12) sh_x[tid / 3][65 + tid % 3] = 0.0f;   // zero pads once
    __syncthreads();

    for (size_t row0 = (size_t)blockIdx.x * 4; row0 < NROWS;
         row0 += (size_t)gridDim.x * 4) {
        __syncthreads();   // previous iteration's reads complete
        sh_x[rsub][jl] = x[(row0 + rsub) * UNITS + jl];
        __syncthreads();
#pragma unroll
        for (int r = 0; r < 4; r++) {
            unsigned long long a0 = 0ull, a1 = 0ull;
            dot33(sh_x[r], wcol, a0, a1);
            g_zpre[(row0 + r) * G4 + tid] = bj + hsum4(a0, a1);
        }
    }
}

// ---------------- kernel 2: persistent recurrence, one block per batch row ----------------
__global__ void __launch_bounds__(288, 1) rec_kernel(const float* __restrict__ W,
                                                     const float* __restrict__ U,
                                                     const float* __restrict__ b) {
    const int j = threadIdx.x;        // 0..287 (260 compute threads)
    const int row = blockIdx.x;       // batch row

    __shared__ __align__(16) float sh_h1[68], sh_h2[68], sh_h3[68];
    __shared__ float sh_z[G4];

    unsigned long long wcol[33], ucol[33];
    float bj = 0.0f;
    if (j < G4) {
#pragma unroll
        for (int m = 0; m < 32; m++) {
            wcol[m] = pack2(W[(2 * m) * G4 + j], W[(2 * m + 1) * G4 + j]);
            ucol[m] = pack2(U[(2 * m) * G4 + j], U[(2 * m + 1) * G4 + j]);
        }
        wcol[32] = pack2(W[64 * G4 + j], 0.0f);
        ucol[32] = pack2(U[64 * G4 + j], 0.0f);
        bj = b[j];
    }
    if (j < 68) { sh_h1[j] = 0.0f; sh_h2[j] = 0.0f; sh_h3[j] = 0.0f; }

    float c1 = 0.0f, c2 = 0.0f, c3 = 0.0f;
    const float* __restrict__ zpre = g_zpre + (size_t)row * SEQ * G4;
    float* __restrict__ h3out = g_h3 + (size_t)row * SEQ * UNITS;

    float zp = (j < G4) ? zpre[j] : 0.0f;           // t = 0 prefetch
    unsigned long long a0 = 0ull, a1 = 0ull;        // accU1 for t=0 (h1 == 0)
    __syncthreads();

    for (int t = 0; t < SEQ; t++) {
        // --- A': finalize layer-1 gates ---
        if (j < G4) sh_z[j] = zp + hsum4(a0, a1);
        __syncthreads();

        // --- B: act L1  ||  accU2 = h2_old @ U  ||  prefetch next zpre ---
        a0 = 0ull; a1 = 0ull;
        if (j < UNITS) {
            float zi = sh_z[j], zf = sh_z[UNITS + j];
            float zg = sh_z[2 * UNITS + j], zo = sh_z[3 * UNITS + j];
            c1 = sigm_f(zf) * c1 + sigm_f(zi) * tanh_f(zg);
            sh_h1[j] = sigm_f(zo) * tanh_f(c1);
        }
        if (j < G4) {
            dot33(sh_h2, ucol, a0, a1);
            int tn = (t + 1 < SEQ) ? t + 1 : t;
            zp = zpre[(size_t)tn * G4 + j];
        }
        __syncthreads();

        // --- C: z2 = accU2 + h1_new @ W + b ---
        if (j < G4) {
            dot33(sh_h1, wcol, a0, a1);
            sh_z[j] = bj + hsum4(a0, a1);
        }
        __syncthreads();

        // --- D: act L2  ||  accU3 = h3_old @ U ---
        a0 = 0ull; a1 = 0ull;
        if (j < UNITS) {
            float zi = sh_z[j], zf = sh_z[UNITS + j];
            float zg = sh_z[2 * UNITS + j], zo = sh_z[3 * UNITS + j];
            c2 = sigm_f(zf) * c2 + sigm_f(zi) * tanh_f(zg);
            sh_h2[j] = sigm_f(zo) * tanh_f(c2);
        }
        if (j < G4) dot33(sh_h3, ucol, a0, a1);
        __syncthreads();

        // --- E: z3 = accU3 + h2_new @ W + b ---
        if (j < G4) {
            dot33(sh_h2, wcol, a0, a1);
            sh_z[j] = bj + hsum4(a0, a1);
        }
        __syncthreads();

        // --- F: act L3 (+ emit h3)  ||  accU1_next = h1 @ U ---
        a0 = 0ull; a1 = 0ull;
        if (j < UNITS) {
            float zi = sh_z[j], zf = sh_z[UNITS + j];
            float zg = sh_z[2 * UNITS + j], zo = sh_z[3 * UNITS + j];
            c3 = sigm_f(zf) * c3 + sigm_f(zi) * tanh_f(zg);
            float hn = sigm_f(zo) * tanh_f(c3);
            sh_h3[j] = hn;
            h3out[(size_t)t * UNITS + j] = hn;
        }
        if (j < G4) dot33(sh_h1, ucol, a0, a1);
        __syncthreads();
    }
}

// ---------------- kernel 3: out = ys @ Wd + bd  (parallel) ----------------
__global__ void __launch_bounds__(G4) dense_kernel(const float* __restrict__ Wd,
                                                   const float* __restrict__ bd,
                                                   float* __restrict__ out) {
    const int tid = threadIdx.x;           // 0..259
    const int rsub = tid / UNITS;          // 0..3
    const int jl = tid - rsub * UNITS;     // 0..64 -> output column

    unsigned long long wdcol[33];
#pragma unroll
    for (int m = 0; m < 32; m++)
        wdcol[m] = pack2(Wd[(2 * m) * UNITS + jl], Wd[(2 * m + 1) * UNITS + jl]);
    wdcol[32] = pack2(Wd[64 * UNITS + jl], 0.0f);
    const float bj = bd[jl];

    __shared__ __align__(16) float sh_y[4][68];
    if (tid < 12) sh_y[tid / 3][65 + tid % 3] = 0.0f;
    __syncthreads();

    for (size_t row0 = (size_t)blockIdx.x * 4; row0 < NROWS;
         row0 += (size_t)gridDim.x * 4) {
        __syncthreads();
        sh_y[rsub][jl] = g_h3[(row0 + rsub) * UNITS + jl];
        __syncthreads();
        unsigned long long a0 = 0ull, a1 = 0ull;
        dot33(sh_y[rsub], wdcol, a0, a1);
        out[(row0 + rsub) * UNITS + jl] = bj + hsum4(a0, a1);
    }
}

// ---------------- launch ----------------
extern "C" void kernel_launch(void* const* d_in, const int* in_sizes, int n_in,
                              void* d_out, int out_size) {
    const float* x  = (const float*)d_in[0];
    const float* W  = (const float*)d_in[1];
    const float* U  = (const float*)d_in[2];
    const float* b  = (const float*)d_in[3];
    const float* Wd = (const float*)d_in[4];
    const float* bd = (const float*)d_in[5];
    float* out = (float*)d_out;

    pre_kernel<<<1184, G4>>>(x, W, b);
    rec_kernel<<<BATCH, 288>>>(W, U, b);
    dense_kernel<<<1184, G4>>>(Wd, bd, out);
}